// round 4
// baseline (speedup 1.0000x reference)
#include <cuda_runtime.h>

#define BATCH 4
#define NN 32768
#define KSEL 1000u
#define NTHREADS 1024
#define EPT 32          // NN / NTHREADS, contiguous per thread
#define VEC 8           // EPT / 4

__device__ unsigned int g_keys[BATCH * NN];

// Order-preserving bijection float -> uint32 (larger float => larger key)
__device__ __forceinline__ unsigned int fkey(float s) {
    unsigned int u = __float_as_uint(s);
    unsigned int mask = (u & 0x80000000u) ? 0xFFFFFFFFu : 0x80000000u;
    return u ^ mask;
}

__global__ __launch_bounds__(NTHREADS, 1)
void selection_kernel(const float* __restrict__ logits,
                      const float* __restrict__ gumbel,
                      float* __restrict__ out)
{
    const int b    = blockIdx.x;
    const int tid  = threadIdx.x;
    const int lane = tid & 31;
    const int wid  = tid >> 5;

    const float*  lrow = logits + (size_t)b * NN;
    const float*  grow = gumbel + (size_t)b * NN;
    unsigned int* krow = g_keys + (size_t)b * NN;

    float* out_values   = out;                                   // [BATCH]
    float* out_logprobs = out + BATCH + (size_t)b * NN;          // row b
    float* out_actions  = out + BATCH + (size_t)BATCH * NN + (size_t)b * NN;

    __shared__ float        s_red[32];
    __shared__ unsigned int s_hist[256];
    __shared__ unsigned int s_wt[8];
    __shared__ int          s_warpsum[32];
    __shared__ float        s_max, s_lse;
    __shared__ unsigned int s_prefix, s_remaining, s_remnext;

    const int base = tid * EPT;
    const float4* l4 = reinterpret_cast<const float4*>(lrow + base);
    const float4* g4 = reinterpret_cast<const float4*>(grow + base);
    uint4*        k4 = reinterpret_cast<uint4*>(krow + base);

    // ---------- Pass 1: keys of (logits + gumbel); running max of logits ----------
    float m = -3.402823466e+38f;
    #pragma unroll
    for (int j = 0; j < VEC; ++j) {
        float4 lv = l4[j];
        float4 gv = g4[j];
        uint4 kv;
        kv.x = fkey(lv.x + gv.x);
        kv.y = fkey(lv.y + gv.y);
        kv.z = fkey(lv.z + gv.z);
        kv.w = fkey(lv.w + gv.w);
        k4[j] = kv;
        m = fmaxf(m, fmaxf(fmaxf(lv.x, lv.y), fmaxf(lv.z, lv.w)));
    }
    #pragma unroll
    for (int o = 16; o > 0; o >>= 1) m = fmaxf(m, __shfl_xor_sync(0xffffffffu, m, o));
    if (lane == 0) s_red[wid] = m;
    __syncthreads();
    if (wid == 0) {
        float v = s_red[lane];
        #pragma unroll
        for (int o = 16; o > 0; o >>= 1) v = fmaxf(v, __shfl_xor_sync(0xffffffffu, v, o));
        if (lane == 0) s_max = v;
    }
    __syncthreads();
    m = s_max;

    // ---------- Pass 2: sum exp(l - m) -> logsumexp; values = sigmoid(m) ----------
    float se = 0.f;
    #pragma unroll
    for (int j = 0; j < VEC; ++j) {
        float4 lv = l4[j];
        se += __expf(lv.x - m) + __expf(lv.y - m) + __expf(lv.z - m) + __expf(lv.w - m);
    }
    #pragma unroll
    for (int o = 16; o > 0; o >>= 1) se += __shfl_xor_sync(0xffffffffu, se, o);
    if (lane == 0) s_red[wid] = se;
    __syncthreads();
    if (wid == 0) {
        float v = s_red[lane];
        #pragma unroll
        for (int o = 16; o > 0; o >>= 1) v += __shfl_xor_sync(0xffffffffu, v, o);
        if (lane == 0) {
            s_lse = m + logf(v);
            out_values[b] = 1.0f / (1.0f + expf(-m));
        }
    }

    // ---------- Radix select: find 1000th largest key (exact) ----------
    if (tid == 0) { s_prefix = 0u; s_remaining = KSEL; }

    #pragma unroll
    for (int pass = 0; pass < 4; ++pass) {
        const int shift = 24 - 8 * pass;
        if (tid == 0 && pass != 0) s_remaining = s_remnext;
        if (tid < 256) s_hist[tid] = 0u;
        __syncthreads();                                        // A

        const unsigned int pref  = s_prefix;
        const unsigned int hmask = (shift == 24) ? 0u : (0xFFFFFFFFu << (shift + 8));
        #pragma unroll
        for (int j = 0; j < VEC; ++j) {
            uint4 kv = k4[j];
            if ((kv.x & hmask) == pref) atomicAdd(&s_hist[(kv.x >> shift) & 0xFFu], 1u);
            if ((kv.y & hmask) == pref) atomicAdd(&s_hist[(kv.y >> shift) & 0xFFu], 1u);
            if ((kv.z & hmask) == pref) atomicAdd(&s_hist[(kv.z >> shift) & 0xFFu], 1u);
            if ((kv.w & hmask) == pref) atomicAdd(&s_hist[(kv.w >> shift) & 0xFFu], 1u);
        }
        __syncthreads();                                        // B

        // Suffix-scan buckets in descending order; pick bucket containing rank.
        unsigned int incl = 0, val = 0;
        if (tid < 256) {
            val = s_hist[255 - tid];
            incl = val;
            #pragma unroll
            for (int o = 1; o < 32; o <<= 1) {
                unsigned int y = __shfl_up_sync(0xffffffffu, incl, o);
                if (lane >= o) incl += y;
            }
            if (lane == 31) s_wt[tid >> 5] = incl;
        }
        __syncthreads();
        if (tid < 256) {
            unsigned int basew = 0;
            #pragma unroll
            for (int w = 0; w < 8; ++w) if (w < (tid >> 5)) basew += s_wt[w];
            incl += basew;
            const unsigned int rem = s_remaining;
            const unsigned int gt  = incl - val;  // keys in strictly-higher buckets
            if (gt < rem && incl >= rem) {        // unique winner
                s_prefix  = pref | ((unsigned int)(255 - tid) << shift);
                s_remnext = rem - gt;
            }
        }
        __syncthreads();                                        // C
    }

    const unsigned int T    = s_prefix;   // exact key value of the K-th largest
    const unsigned int need = s_remnext;  // how many ties (==T) to take, lowest index first

    // ---------- Exact rank of ties by global index (block exclusive scan) ----------
    int eq = 0;
    #pragma unroll
    for (int j = 0; j < VEC; ++j) {
        uint4 kv = k4[j];
        eq += (kv.x == T) + (kv.y == T) + (kv.z == T) + (kv.w == T);
    }
    int incl = eq;
    #pragma unroll
    for (int o = 1; o < 32; o <<= 1) {
        int y = __shfl_up_sync(0xffffffffu, incl, o);
        if (lane >= o) incl += y;
    }
    if (lane == 31) s_warpsum[wid] = incl;
    __syncthreads();
    if (wid == 0) {
        int v = s_warpsum[lane];
        int wi = v;
        #pragma unroll
        for (int o = 1; o < 32; o <<= 1) {
            int y = __shfl_up_sync(0xffffffffu, wi, o);
            if (lane >= o) wi += y;
        }
        s_warpsum[lane] = wi - v;   // exclusive base per warp
    }
    __syncthreads();
    unsigned int r = (unsigned int)(s_warpsum[wid] + (incl - eq));

    // ---------- Final pass: write actions and logprobs ----------
    const float lse = s_lse;
    float4* lp4 = reinterpret_cast<float4*>(out_logprobs + base);
    float4* ac4 = reinterpret_cast<float4*>(out_actions + base);
    #pragma unroll
    for (int j = 0; j < VEC; ++j) {
        uint4 kv = k4[j];
        float4 lv = l4[j];
        float4 av, pv;

        float a;
        a = (kv.x > T) ? 1.f : 0.f;
        if (kv.x == T) { a = (r < need) ? 1.f : 0.f; ++r; }
        av.x = a; pv.x = a * (lv.x - lse);

        a = (kv.y > T) ? 1.f : 0.f;
        if (kv.y == T) { a = (r < need) ? 1.f : 0.f; ++r; }
        av.y = a; pv.y = a * (lv.y - lse);

        a = (kv.z > T) ? 1.f : 0.f;
        if (kv.z == T) { a = (r < need) ? 1.f : 0.f; ++r; }
        av.z = a; pv.z = a * (lv.z - lse);

        a = (kv.w > T) ? 1.f : 0.f;
        if (kv.w == T) { a = (r < need) ? 1.f : 0.f; ++r; }
        av.w = a; pv.w = a * (lv.w - lse);

        ac4[j] = av;
        lp4[j] = pv;
    }
}

extern "C" void kernel_launch(void* const* d_in, const int* in_sizes, int n_in,
                              void* d_out, int out_size) {
    const float* logits = (const float*)d_in[0];
    const float* gumbel = (const float*)d_in[1];
    float* out = (float*)d_out;
    selection_kernel<<<BATCH, NTHREADS>>>(logits, gumbel, out);
}

// round 5
// speedup vs baseline: 4.5275x; 4.5275x over previous
#include <cuda_runtime.h>
#include <cooperative_groups.h>
namespace cg = cooperative_groups;

#define BATCH 4
#define NN 32768
#define KSEL 1000u
#define CLUSTER 8
#define NTHREADS 512
#define NWARP (NTHREADS / 32)
#define EPR (NN / CLUSTER)          // 4096 elements per CTA
#define EPT 8                        // elements per thread

__global__ void __cluster_dims__(CLUSTER, 1, 1) __launch_bounds__(NTHREADS, 1)
selection_kernel(const float* __restrict__ logits,
                 const float* __restrict__ gumbel,
                 float* __restrict__ out)
{
    cg::cluster_group cl = cg::this_cluster();
    const int tid   = threadIdx.x;
    const int lane  = tid & 31;
    const int wid   = tid >> 5;
    const int b     = blockIdx.x / CLUSTER;
    const int crank = blockIdx.x % CLUSTER;   // == cluster rank

    __shared__ unsigned s_hist[256];
    __shared__ unsigned s_gh[2][256];     // CTA0's copies are the cluster accumulators
    __shared__ float    s_pm[CLUSTER], s_ps[CLUSTER];   // per-CTA (max, sumexp) partials
    __shared__ unsigned s_res[2];         // CTA0 authoritative: {prefix, remaining}
    __shared__ unsigned s_cur[2];         // local copy
    __shared__ float    s_lse0;           // CTA0 authoritative lse
    __shared__ float    s_lse;            // local copy
    __shared__ float    s_redf[NWARP];
    __shared__ int      s_redi[NWARP + 1];
    __shared__ unsigned s_wt[8];
    __shared__ unsigned s_tc[CLUSTER];    // tie counts per CTA (broadcast to all)

    const size_t roff = (size_t)b * NN + (size_t)crank * EPR + (size_t)tid * EPT;
    const float4* l4 = reinterpret_cast<const float4*>(logits + roff);
    const float4* g4 = reinterpret_cast<const float4*>(gumbel + roff);

    // ---------- load once; keys + logits live in registers ----------
    float l[EPT]; unsigned k[EPT];
    {
        float4 a0 = l4[0], a1 = l4[1], c0 = g4[0], c1 = g4[1];
        l[0]=a0.x; l[1]=a0.y; l[2]=a0.z; l[3]=a0.w;
        l[4]=a1.x; l[5]=a1.y; l[6]=a1.z; l[7]=a1.w;
        float g[EPT] = {c0.x,c0.y,c0.z,c0.w,c1.x,c1.y,c1.z,c1.w};
        #pragma unroll
        for (int j = 0; j < EPT; ++j) {
            unsigned u = __float_as_uint(l[j] + g[j]);
            k[j] = u ^ ((u & 0x80000000u) ? 0xFFFFFFFFu : 0x80000000u);
        }
    }

    if (tid < 256) { s_hist[tid] = 0u; s_gh[0][tid] = 0u; s_gh[1][tid] = 0u; }
    if (crank == 0 && tid == 300) { s_res[0] = 0u; s_res[1] = KSEL; }

    // ---------- per-CTA max ----------
    float m = -3.402823466e+38f;
    #pragma unroll
    for (int j = 0; j < EPT; ++j) m = fmaxf(m, l[j]);
    #pragma unroll
    for (int o = 16; o; o >>= 1) m = fmaxf(m, __shfl_xor_sync(~0u, m, o));
    if (lane == 0) s_redf[wid] = m;
    __syncthreads();
    if (wid == 0) {
        float v = (lane < NWARP) ? s_redf[lane] : -3.402823466e+38f;
        #pragma unroll
        for (int o = 16; o; o >>= 1) v = fmaxf(v, __shfl_xor_sync(~0u, v, o));
        if (lane == 0) s_redf[0] = v;
    }
    __syncthreads();
    const float mb = s_redf[0];
    __syncthreads();   // protect s_redf reuse below

    // ---------- per-CTA sum exp(l - mb); pass-0 local histogram ----------
    float se = 0.f;
    #pragma unroll
    for (int j = 0; j < EPT; ++j) se += __expf(l[j] - mb);
    #pragma unroll
    for (int o = 16; o; o >>= 1) se += __shfl_xor_sync(~0u, se, o);
    if (lane == 0) s_redf[wid] = se;

    #pragma unroll
    for (int j = 0; j < EPT; ++j) atomicAdd(&s_hist[k[j] >> 24], 1u);
    __syncthreads();

    if (wid == 0) {
        float v = (lane < NWARP) ? s_redf[lane] : 0.f;
        #pragma unroll
        for (int o = 16; o; o >>= 1) v += __shfl_xor_sync(~0u, v, o);
        if (lane == 0) {
            float* pm0 = cl.map_shared_rank(s_pm, 0);
            float* ps0 = cl.map_shared_rank(s_ps, 0);
            pm0[crank] = mb;
            ps0[crank] = v;
        }
    }
    // push pass-0 bins into CTA0
    if (tid < 256) {
        unsigned c = s_hist[tid];
        if (c) atomicAdd(cl.map_shared_rank(s_gh[0], 0) + tid, c);
    }
    cl.sync();   // softmax partials + pass-0 histogram visible at CTA0

    // ---------- 4 radix passes (8-bit digits, MSB first) ----------
    #pragma unroll
    for (int pass = 0; pass < 4; ++pass) {
        const int shift = 24 - 8 * pass;

        if (crank == 0) {
            unsigned* gh = s_gh[pass & 1];
            const unsigned rem = s_res[1];
            unsigned val = 0, incl = 0;
            if (tid < 256) {
                val = gh[255 - tid];
                incl = val;
                #pragma unroll
                for (int o = 1; o < 32; o <<= 1) {
                    unsigned y = __shfl_up_sync(~0u, incl, o);
                    if (lane >= o) incl += y;
                }
                if (lane == 31) s_wt[tid >> 5] = incl;
            }
            if (pass == 0 && tid == NTHREADS - 1) {
                // combine online-softmax partials; write values output
                float M = -3.402823466e+38f;
                #pragma unroll
                for (int i = 0; i < CLUSTER; ++i) M = fmaxf(M, s_pm[i]);
                float S = 0.f;
                #pragma unroll
                for (int i = 0; i < CLUSTER; ++i) S += s_ps[i] * __expf(s_pm[i] - M);
                s_lse0 = M + logf(S);
                out[b] = 1.0f / (1.0f + expf(-M));
            }
            __syncthreads();
            if (tid < 256) {
                unsigned base = 0;
                #pragma unroll
                for (int w = 0; w < 8; ++w) if (w < (tid >> 5)) base += s_wt[w];
                incl += base;
                const unsigned gt = incl - val;
                if (gt < rem && incl >= rem) {
                    s_res[0] |= (unsigned)(255 - tid) << shift;
                    s_res[1]  = rem - gt;
                }
                gh[tid] = 0u;   // reset accumulator for pass+2
            }
        }
        cl.sync();   // selection result visible cluster-wide

        if (tid < 2) s_cur[tid] = cl.map_shared_rank(s_res, 0)[tid];
        if (pass == 0 && tid == 2) s_lse = *cl.map_shared_rank(&s_lse0, 0);
        __syncthreads();

        if (pass < 3) {
            const int nshift = shift - 8;
            const unsigned pref  = s_cur[0];
            const unsigned hmask = 0xFFFFFFFFu << (nshift + 8);
            if (tid < 256) s_hist[tid] = 0u;
            __syncthreads();
            #pragma unroll
            for (int j = 0; j < EPT; ++j)
                if ((k[j] & hmask) == pref)
                    atomicAdd(&s_hist[(k[j] >> nshift) & 0xFFu], 1u);
            __syncthreads();
            if (tid < 256) {
                unsigned c = s_hist[tid];
                if (c) atomicAdd(cl.map_shared_rank(s_gh[(pass + 1) & 1], 0) + tid, c);
            }
            cl.sync();   // next pass's histogram complete at CTA0
        }
    }

    const unsigned T    = s_cur[0];   // exact key of the K-th largest
    const unsigned need = s_cur[1];   // ties (==T) to accept, lowest index first

    // ---------- tie ranks: block scan + cluster exclusive base ----------
    int eq = 0;
    #pragma unroll
    for (int j = 0; j < EPT; ++j) eq += (k[j] == T);
    int incl = eq;
    #pragma unroll
    for (int o = 1; o < 32; o <<= 1) {
        int y = __shfl_up_sync(~0u, incl, o);
        if (lane >= o) incl += y;
    }
    if (lane == 31) s_redi[wid] = incl;
    __syncthreads();
    if (wid == 0) {
        int v = (lane < NWARP) ? s_redi[lane] : 0;
        int wi = v;
        #pragma unroll
        for (int o = 1; o < 32; o <<= 1) {
            int y = __shfl_up_sync(~0u, wi, o);
            if (lane >= o) wi += y;
        }
        if (lane < NWARP) s_redi[lane] = wi - v;   // exclusive warp bases
        if (lane == 31) s_redi[NWARP] = wi;        // CTA tie total
    }
    __syncthreads();
    if (tid < CLUSTER) {
        unsigned* p = cl.map_shared_rank(s_tc, tid);
        p[crank] = (unsigned)s_redi[NWARP];        // broadcast my total to all CTAs
    }
    cl.sync();

    unsigned tbase = 0;
    #pragma unroll
    for (int r2 = 0; r2 < CLUSTER; ++r2) if (r2 < crank) tbase += s_tc[r2];
    unsigned r = tbase + (unsigned)(s_redi[wid] + incl - eq);

    // ---------- final write: actions + logprobs ----------
    const float lse = s_lse;
    float a[EPT];
    #pragma unroll
    for (int j = 0; j < EPT; ++j) {
        float x = (k[j] > T) ? 1.f : 0.f;
        if (k[j] == T) { x = (r < need) ? 1.f : 0.f; ++r; }
        a[j] = x;
    }
    float* lp = out + BATCH + roff;
    float* ac = out + BATCH + (size_t)BATCH * NN + roff;
    float4 p0 = make_float4(a[0]*(l[0]-lse), a[1]*(l[1]-lse), a[2]*(l[2]-lse), a[3]*(l[3]-lse));
    float4 p1 = make_float4(a[4]*(l[4]-lse), a[5]*(l[5]-lse), a[6]*(l[6]-lse), a[7]*(l[7]-lse));
    float4 a0 = make_float4(a[0], a[1], a[2], a[3]);
    float4 a1 = make_float4(a[4], a[5], a[6], a[7]);
    reinterpret_cast<float4*>(lp)[0] = p0;
    reinterpret_cast<float4*>(lp)[1] = p1;
    reinterpret_cast<float4*>(ac)[0] = a0;
    reinterpret_cast<float4*>(ac)[1] = a1;
}

extern "C" void kernel_launch(void* const* d_in, const int* in_sizes, int n_in,
                              void* d_out, int out_size) {
    const float* logits = (const float*)d_in[0];
    const float* gumbel = (const float*)d_in[1];
    float* out = (float*)d_out;
    selection_kernel<<<BATCH * CLUSTER, NTHREADS>>>(logits, gumbel, out);
}